// round 1
// baseline (speedup 1.0000x reference)
#include <cuda_runtime.h>
#include <math.h>

#define TT 2048      // tokens = B*S
#define EE 8         // experts
#define HH 768       // hidden
#define FF 3072      // ffn hidden
#define NSLOT (TT*2) // token-expert slots (top-2)

// Scratch (allocation-free rule: __device__ globals)
__device__ float g_hmid[(size_t)NSLOT * FF];   // ~50 MB
__device__ int   g_cnt[EE];
__device__ int   g_list[EE * TT];              // slot ids per expert
__device__ float g_slot_w[NSLOT];              // combine weight per slot

__global__ void init_kernel(float* out, int out_size) {
    int i = blockIdx.x * blockDim.x + threadIdx.x;
    if (i < out_size) out[i] = 0.0f;
    if (i < EE) g_cnt[i] = 0;
}

// One warp per token: 8 logits, top-2, softmax over the pair, scatter to lists.
__global__ void router_kernel(const float* __restrict__ x,
                              const float* __restrict__ rw) {
    int gw   = (blockIdx.x * blockDim.x + threadIdx.x) >> 5;
    int lane = threadIdx.x & 31;
    if (gw >= TT) return;
    const float* xt = x + (size_t)gw * HH;
    float xv[HH / 32];
#pragma unroll
    for (int i = 0; i < HH / 32; i++) xv[i] = xt[lane + 32 * i];
    float lg[EE];
#pragma unroll
    for (int e = 0; e < EE; e++) {
        const float* w = rw + (size_t)e * HH;
        float s = 0.0f;
#pragma unroll
        for (int i = 0; i < HH / 32; i++) s = fmaf(xv[i], w[lane + 32 * i], s);
#pragma unroll
        for (int o = 16; o; o >>= 1) s += __shfl_xor_sync(0xffffffffu, s, o);
        lg[e] = s;
    }
    if (lane == 0) {
        int i0 = 0;
#pragma unroll
        for (int e = 1; e < EE; e++) if (lg[e] > lg[i0]) i0 = e;
        int i1 = (i0 == 0) ? 1 : 0;
#pragma unroll
        for (int e = 0; e < EE; e++) {
            if (e == i0 || e == i1) continue;
            if (lg[e] > lg[i1]) i1 = e;
        }
        float ex = expf(lg[i1] - lg[i0]);       // v1 <= v0, stable
        float inv = 1.0f / (1.0f + ex);
        g_slot_w[gw * 2]     = inv;             // prob of top-1
        g_slot_w[gw * 2 + 1] = ex * inv;        // prob of top-2
        int p = atomicAdd(&g_cnt[i0], 1); g_list[i0 * TT + p] = gw * 2;
        int q = atomicAdd(&g_cnt[i1], 1); g_list[i1 * TT + q] = gw * 2 + 1;
    }
}

// Grouped expert GEMM. A and B are both K-contiguous (row-major over K).
// MODE 0: A = x[token], W = w1[e] -> gelu -> g_hmid[slot]        (KD=HH, ND=FF)
// MODE 1: A = g_hmid[slot], W = w2[e] -> weighted atomicAdd out  (KD=FF, ND=HH)
template <int MODE, int KD, int ND>
__global__ __launch_bounds__(256) void expert_gemm(
    const float* __restrict__ Xtok,
    const float* __restrict__ W,
    const float* __restrict__ bias,
    float* __restrict__ Out) {
    const int BM = 128, BN = 64, BK = 16;
    int e   = blockIdx.z;
    int cnt = g_cnt[e];
    int m0  = blockIdx.y * BM;
    if (m0 >= cnt) return;
    int n0  = blockIdx.x * BN;

    __shared__ float As[BK][BM + 4];
    __shared__ float Bs[BK][BN + 4];
    __shared__ int   s_slot[BM];

    int tid = threadIdx.x;
    for (int i = tid; i < BM; i += 256) {
        int r = m0 + i;
        s_slot[i] = g_list[e * TT + (r < cnt ? r : cnt - 1)];
    }
    __syncthreads();

    const float* Wb = W + (size_t)e * ND * KD;
    int tx = tid & 15;   // n-direction: 16 threads * 4 = 64 cols
    int ty = tid >> 4;   // m-direction: 16 threads * 8 = 128 rows

    float acc[8][4];
#pragma unroll
    for (int m = 0; m < 8; m++)
#pragma unroll
        for (int n = 0; n < 4; n++) acc[m][n] = 0.0f;

    for (int k0 = 0; k0 < KD; k0 += BK) {
        // A tile: 128x16 floats, 2 float4 per thread, stored transposed
#pragma unroll
        for (int j = 0; j < 2; j++) {
            int idx = tid + j * 256;
            int row = idx >> 2;
            int kq  = (idx & 3) * 4;
            int slot = s_slot[row];
            const float* ar = (MODE == 0)
                ? (Xtok + (size_t)(slot >> 1) * KD)
                : (g_hmid + (size_t)slot * KD);
            float4 v = *(const float4*)(ar + k0 + kq);
            As[kq + 0][row] = v.x; As[kq + 1][row] = v.y;
            As[kq + 2][row] = v.z; As[kq + 3][row] = v.w;
        }
        // B tile: 64x16 floats, 1 float4 per thread
        {
            int row = tid >> 2;
            int kq  = (tid & 3) * 4;
            float4 v = *(const float4*)(Wb + (size_t)(n0 + row) * KD + k0 + kq);
            Bs[kq + 0][row] = v.x; Bs[kq + 1][row] = v.y;
            Bs[kq + 2][row] = v.z; Bs[kq + 3][row] = v.w;
        }
        __syncthreads();
#pragma unroll
        for (int k = 0; k < BK; k++) {
            float a[8], b[4];
            *(float4*)(a)     = *(const float4*)(&As[k][ty * 8]);
            *(float4*)(a + 4) = *(const float4*)(&As[k][ty * 8 + 4]);
            *(float4*)(b)     = *(const float4*)(&Bs[k][tx * 4]);
#pragma unroll
            for (int m = 0; m < 8; m++)
#pragma unroll
                for (int n = 0; n < 4; n++)
                    acc[m][n] = fmaf(a[m], b[n], acc[m][n]);
        }
        __syncthreads();
    }

    // Epilogue
#pragma unroll
    for (int m = 0; m < 8; m++) {
        int rl = ty * 8 + m;
        if (m0 + rl >= cnt) continue;
        int slot = s_slot[rl];
#pragma unroll
        for (int n = 0; n < 4; n++) {
            int nc = n0 + tx * 4 + n;
            float v = acc[m][n] + bias[(size_t)e * ND + nc];
            if (MODE == 0) {
                // exact GELU: 0.5*v*(1+erf(v/sqrt(2)))
                v = 0.5f * v * (1.0f + erff(v * 0.70710678118654752f));
                g_hmid[(size_t)slot * ND + nc] = v;
            } else {
                float wgt = g_slot_w[slot];
                atomicAdd(&Out[(size_t)(slot >> 1) * ND + nc], wgt * v);
            }
        }
    }
}

extern "C" void kernel_launch(void* const* d_in, const int* in_sizes, int n_in,
                              void* d_out, int out_size) {
    const float* x  = (const float*)d_in[0];  // [T, H]
    const float* rw = (const float*)d_in[1];  // [E, H]
    const float* w1 = (const float*)d_in[2];  // [E, F, H]
    const float* b1 = (const float*)d_in[3];  // [E, F]
    const float* w2 = (const float*)d_in[4];  // [E, H, F]
    const float* b2 = (const float*)d_in[5];  // [E, H]
    float* out = (float*)d_out;               // [T, H]

    init_kernel<<<(out_size + 255) / 256, 256>>>(out, out_size);
    router_kernel<<<(TT * 32) / 256, 256>>>(x, rw);

    dim3 g1(FF / 64, (TT + 127) / 128, EE);
    expert_gemm<0, HH, FF><<<g1, 256>>>(x, w1, b1, out);

    dim3 g2(HH / 64, (TT + 127) / 128, EE);
    expert_gemm<1, FF, HH><<<g2, 256>>>(x, w2, b2, out);
}

// round 3
// speedup vs baseline: 3.2817x; 3.2817x over previous
#include <cuda_runtime.h>
#include <math.h>
#include <cstdint>

#define TT 2048      // tokens = B*S
#define EE 8         // experts
#define HH 768       // hidden
#define FF 3072      // ffn hidden

// ---------------- scratch (__device__ globals: allocation-free rule) --------
__device__ float g_hmid[(size_t)TT * 2 * FF];   // 50 MB
__device__ int   g_cnt[EE];
__device__ int   g_list[EE * TT];
__device__ float g_slot_w[TT * 2];

// ---------------- helpers ----------------------------------------------------
__device__ __forceinline__ uint32_t smem_u32(const void* p) {
    uint32_t a;
    asm("{ .reg .u64 t; cvta.to.shared.u64 t, %1; cvt.u32.u64 %0, t; }" : "=r"(a) : "l"(p));
    return a;
}
__device__ __forceinline__ void cpa16(uint32_t dst, const void* src) {
    asm volatile("cp.async.cg.shared.global [%0], [%1], 16;\n" :: "r"(dst), "l"(src));
}
__device__ __forceinline__ void cpa_commit() { asm volatile("cp.async.commit_group;\n" ::: "memory"); }
__device__ __forceinline__ void cpa_wait1()  { asm volatile("cp.async.wait_group 1;\n" ::: "memory"); }

__device__ __forceinline__ void ldsm4(uint32_t r[4], uint32_t addr) {
    asm volatile("ldmatrix.sync.aligned.m8n8.x4.shared.b16 {%0,%1,%2,%3}, [%4];"
                 : "=r"(r[0]), "=r"(r[1]), "=r"(r[2]), "=r"(r[3]) : "r"(addr));
}
__device__ __forceinline__ uint32_t tf32q(uint32_t x) {
    uint32_t o;
    asm("cvt.rna.tf32.f32 %0, %1;" : "=r"(o) : "f"(__uint_as_float(x)));
    return o;
}
__device__ __forceinline__ void mma8(float c[4], const uint32_t a[4],
                                     uint32_t b0, uint32_t b1) {
    asm volatile(
        "mma.sync.aligned.m16n8k8.row.col.f32.tf32.tf32.f32 "
        "{%0,%1,%2,%3}, {%4,%5,%6,%7}, {%8,%9}, {%0,%1,%2,%3};"
        : "+f"(c[0]), "+f"(c[1]), "+f"(c[2]), "+f"(c[3])
        : "r"(a[0]), "r"(a[1]), "r"(a[2]), "r"(a[3]), "r"(b0), "r"(b1));
}

// ---------------- init / router ----------------------------------------------
__global__ void init_kernel(float* out, int out_size) {
    int i = blockIdx.x * blockDim.x + threadIdx.x;
    if (i < out_size) out[i] = 0.0f;
    if (i < EE) g_cnt[i] = 0;
}

__global__ void router_kernel(const float* __restrict__ x,
                              const float* __restrict__ rw) {
    int gw   = (blockIdx.x * blockDim.x + threadIdx.x) >> 5;
    int lane = threadIdx.x & 31;
    if (gw >= TT) return;
    const float* xt = x + (size_t)gw * HH;
    float xv[HH / 32];
#pragma unroll
    for (int i = 0; i < HH / 32; i++) xv[i] = xt[lane + 32 * i];
    float lg[EE];
#pragma unroll
    for (int e = 0; e < EE; e++) {
        const float* w = rw + (size_t)e * HH;
        float s = 0.0f;
#pragma unroll
        for (int i = 0; i < HH / 32; i++) s = fmaf(xv[i], w[lane + 32 * i], s);
#pragma unroll
        for (int o = 16; o; o >>= 1) s += __shfl_xor_sync(0xffffffffu, s, o);
        lg[e] = s;
    }
    if (lane == 0) {
        int i0 = 0;
#pragma unroll
        for (int e = 1; e < EE; e++) if (lg[e] > lg[i0]) i0 = e;
        int i1 = (i0 == 0) ? 1 : 0;
#pragma unroll
        for (int e = 0; e < EE; e++) {
            if (e == i0 || e == i1) continue;
            if (lg[e] > lg[i1]) i1 = e;
        }
        float ex = expf(lg[i1] - lg[i0]);
        float inv = 1.0f / (1.0f + ex);
        g_slot_w[gw * 2]     = inv;
        g_slot_w[gw * 2 + 1] = ex * inv;
        int p = atomicAdd(&g_cnt[i0], 1); g_list[i0 * TT + p] = gw * 2;
        int q = atomicAdd(&g_cnt[i1], 1); g_list[i1 * TT + q] = gw * 2 + 1;
    }
}

// ---------------- mma.sync tf32 grouped GEMM ---------------------------------
// MODE 0: A = x[token] (param), W = w1[e] -> bias + GELU -> g_hmid[slot]
// MODE 1: A = g_hmid[slot],     W = w2[e] -> weighted atomicAdd into Out (split-K)
template <int MODE, int KD, int ND, int NSPLIT>
__global__ __launch_bounds__(256, 2) void moe_gemm(
    const float* __restrict__ Asrc, const float* __restrict__ W,
    const float* __restrict__ bias, float* __restrict__ Out) {
    constexpr int BM = 128, BN = 128, BK = 32;
    constexpr int KSP = KD / NSPLIT;
    constexpr int NSLAB = KSP / BK;
    constexpr int STAGE = (BM + BN) * BK * 4;   // 32 KB

    extern __shared__ char dsm[];
    __shared__ int s_slot[BM];

    int e = blockIdx.z / NSPLIT, split = blockIdx.z % NSPLIT;
    int cnt = g_cnt[e];
    int m0 = blockIdx.y * BM;
    if (m0 >= cnt) return;
    int n0 = blockIdx.x * BN;
    int kbase = split * KSP;
    int tid = threadIdx.x, lane = tid & 31, wid = tid >> 5;
    int wm = (wid & 3) * 32, wn = (wid >> 2) * 64;

    const float* __restrict__ Ap = (MODE == 0) ? Asrc : g_hmid;
    const float* __restrict__ Wb = W + (size_t)e * ND * KD;

    for (int i = tid; i < BM; i += 256) {
        int r = m0 + i;
        s_slot[i] = g_list[e * TT + (r < cnt ? r : cnt - 1)];
    }
    __syncthreads();

    uint32_t sb = (smem_u32(dsm) + 127u) & ~127u;

    auto fill = [&](int st, int s) {
        int k0 = kbase + s * BK;
        uint32_t as = sb + st * STAGE;
        uint32_t bs = as + BM * 128;
#pragma unroll
        for (int j = 0; j < 4; j++) {
            int idx = tid + j * 256;
            int r = idx >> 3, c = idx & 7;
            size_t arow = (MODE == 0) ? (size_t)(s_slot[r] >> 1) : (size_t)s_slot[r];
            cpa16(as + r * 128 + ((c * 16) ^ ((r & 7) << 4)),
                  Ap + arow * KD + k0 + c * 4);
        }
#pragma unroll
        for (int j = 0; j < 4; j++) {
            int idx = tid + j * 256;
            int r = idx >> 3, c = idx & 7;
            cpa16(bs + r * 128 + ((c * 16) ^ ((r & 7) << 4)),
                  Wb + (size_t)(n0 + r) * KD + k0 + c * 4);
        }
    };

    fill(0, 0); cpa_commit();
    fill(1, 1); cpa_commit();

    float acc[2][8][4];
#pragma unroll
    for (int mt = 0; mt < 2; mt++)
#pragma unroll
        for (int nt = 0; nt < 8; nt++)
#pragma unroll
            for (int q = 0; q < 4; q++) acc[mt][nt][q] = 0.0f;

    int a_row = lane & 15;            // row within m16 tile
    int a_kx  = (lane >> 4) << 4;     // 0 or 16 bytes
    int b_row = lane & 7;             // row within n8 tile
    int b_kx  = (lane >> 3) << 4;     // 0,16,32,48 bytes

    for (int s = 0; s < NSLAB; s++) {
        cpa_wait1();
        __syncthreads();
        if (s + 2 < NSLAB) fill((s + 2) % 3, s + 2);
        cpa_commit();

        uint32_t ab = sb + (s % 3) * STAGE;
        uint32_t bb = ab + BM * 128;
#pragma unroll
        for (int kh = 0; kh < 2; kh++) {          // 64-byte k-halves of the slab
            uint32_t b[8][4];
#pragma unroll
            for (int nt = 0; nt < 8; nt++) {
                int row = wn + nt * 8 + b_row;
                int kb  = kh * 64 + b_kx;
                ldsm4(b[nt], bb + row * 128 + (kb ^ ((row & 7) << 4)));
            }
#pragma unroll
            for (int nt = 0; nt < 8; nt++)
#pragma unroll
                for (int q = 0; q < 4; q++) b[nt][q] = tf32q(b[nt][q]);
#pragma unroll
            for (int ks = 0; ks < 2; ks++) {      // k8 steps within the half
                uint32_t a[2][4];
#pragma unroll
                for (int mt = 0; mt < 2; mt++) {
                    int row = wm + mt * 16 + a_row;
                    int kb  = kh * 64 + ks * 32 + a_kx;
                    ldsm4(a[mt], ab + row * 128 + (kb ^ ((row & 7) << 4)));
#pragma unroll
                    for (int q = 0; q < 4; q++) a[mt][q] = tf32q(a[mt][q]);
                }
#pragma unroll
                for (int mt = 0; mt < 2; mt++)
#pragma unroll
                    for (int nt = 0; nt < 8; nt++)
                        mma8(acc[mt][nt], a[mt], b[nt][ks * 2], b[nt][ks * 2 + 1]);
            }
        }
    }

    // ---------------- epilogue ----------------
    int g = lane >> 2, tig = lane & 3;
#pragma unroll
    for (int mt = 0; mt < 2; mt++) {
#pragma unroll
        for (int half = 0; half < 2; half++) {
            int rl = wm + mt * 16 + g + half * 8;
            if (m0 + rl >= cnt) continue;
            int slot = s_slot[rl];
            if (MODE == 0) {
                float* dst = g_hmid + (size_t)slot * ND;
                const float* bp = bias + (size_t)e * ND;
#pragma unroll
                for (int nt = 0; nt < 8; nt++) {
                    int col = n0 + wn + nt * 8 + 2 * tig;
                    float v0 = acc[mt][nt][half * 2 + 0] + bp[col];
                    float v1 = acc[mt][nt][half * 2 + 1] + bp[col + 1];
                    v0 = 0.5f * v0 * (1.0f + erff(v0 * 0.70710678118654752f));
                    v1 = 0.5f * v1 * (1.0f + erff(v1 * 0.70710678118654752f));
                    *(float2*)(dst + col) = make_float2(v0, v1);
                }
            } else {
                float wgt = g_slot_w[slot];
                float* dst = Out + (size_t)(slot >> 1) * ND;
                const float* bp = bias + (size_t)e * ND;
#pragma unroll
                for (int nt = 0; nt < 8; nt++) {
                    int col = n0 + wn + nt * 8 + 2 * tig;
                    float v0 = acc[mt][nt][half * 2 + 0] + (split == 0 ? bp[col] : 0.0f);
                    float v1 = acc[mt][nt][half * 2 + 1] + (split == 0 ? bp[col + 1] : 0.0f);
                    atomicAdd(dst + col,     wgt * v0);
                    atomicAdd(dst + col + 1, wgt * v1);
                }
            }
        }
    }
}

// ---------------- launcher ---------------------------------------------------
extern "C" void kernel_launch(void* const* d_in, const int* in_sizes, int n_in,
                              void* d_out, int out_size) {
    const float* x  = (const float*)d_in[0];
    const float* rw = (const float*)d_in[1];
    const float* w1 = (const float*)d_in[2];
    const float* b1 = (const float*)d_in[3];
    const float* w2 = (const float*)d_in[4];
    const float* b2 = (const float*)d_in[5];
    float* out = (float*)d_out;

    const int SMEM = 3 * 32768 + 128;
    cudaFuncSetAttribute(moe_gemm<0, HH, FF, 1>,
                         cudaFuncAttributeMaxDynamicSharedMemorySize, SMEM);
    cudaFuncSetAttribute(moe_gemm<1, FF, HH, 4>,
                         cudaFuncAttributeMaxDynamicSharedMemorySize, SMEM);

    init_kernel<<<(out_size + 255) / 256, 256>>>(out, out_size);
    router_kernel<<<(TT * 32) / 256, 256>>>(x, rw);

    // GEMM1: [4096-ish slots grouped by expert] x w1^T -> GELU -> hmid
    dim3 g1(FF / 128, (TT + 127) / 128, EE);
    moe_gemm<0, HH, FF, 1><<<g1, 256, SMEM>>>(x, w1, b1, out);

    // GEMM2: hmid x w2^T -> weighted scatter-add into out (split-K = 4)
    dim3 g2(HH / 128, (TT + 127) / 128, EE * 4);
    moe_gemm<1, FF, HH, 4><<<g2, 256, SMEM>>>(x, w2, b2, out);
}